// round 17
// baseline (speedup 1.0000x reference)
#include <cuda_runtime.h>
#include <cuda_fp16.h>
#include <math.h>

#define BATCH   4
#define TQ      2048
#define TK      2048
#define DMODEL  1024
#define NHEADS  16
#define HDIM    64
#define MROWS   (BATCH * TQ)   // 8192
#define LOG2E   1.4426950408889634f

// ---------------- scratch (__device__ globals; no allocation allowed) -------
__device__ __half h_Q[MROWS * DMODEL];   // (b,h,t,hd-interleaved), prescaled log2e/8
__device__ __half h_K[MROWS * DMODEL];   // (b,h,t,hd-interleaved)
__device__ __half h_V[MROWS * DMODEL];   // (b,h,hd,t-interleaved)  (V^T)
__device__ __half h_O[MROWS * DMODEL];   // (b,t,dmodel-interleaved)
__device__ __half h_Xq[MROWS * DMODEL];
__device__ __half h_Xkv[MROWS * DMODEL];
__device__ __half h_Wq[DMODEL * DMODEL];
__device__ __half h_Wk[DMODEL * DMODEL];
__device__ __half h_Wv[DMODEL * DMODEL];
__device__ __half h_Wo[DMODEL * DMODEL];
__device__ __half h_Mask[TQ * TK];       // additive mask, fp16
__device__ int    g_flags;               // bit0: mask nonzero, bit1: kpm nonzero

// ---------------- helpers ----------------------------------------------------
__device__ __forceinline__ void mma_f16(float* d, const unsigned* a, const unsigned* b) {
    asm volatile(
        "mma.sync.aligned.m16n8k16.row.col.f32.f16.f16.f32 "
        "{%0,%1,%2,%3}, {%4,%5,%6,%7}, {%8,%9}, {%0,%1,%2,%3};"
        : "+f"(d[0]), "+f"(d[1]), "+f"(d[2]), "+f"(d[3])
        : "r"(a[0]), "r"(a[1]), "r"(a[2]), "r"(a[3]), "r"(b[0]), "r"(b[1]));
}

__device__ __forceinline__ void cp16(void* smem_dst, const void* gmem_src) {
    unsigned s = (unsigned)__cvta_generic_to_shared(smem_dst);
    asm volatile("cp.async.cg.shared.global [%0], [%1], 16;" :: "r"(s), "l"(gmem_src));
}

__device__ __forceinline__ float ex2f(float x) {
    float r;
    asm("ex2.approx.f32 %0, %1;" : "=f"(r) : "f"(x));
    return r;
}

__device__ __forceinline__ int islot(int j) { return (j < 4) ? 2 * j : 2 * j - 7; }

// ---------------- pre-convert --------------------------------------------------
__device__ __forceinline__ void cvt_body(const float* __restrict__ src,
                                         __half* __restrict__ dst, int i8, float scale)
{
    float4 v0 = *(const float4*)&src[i8];
    float4 v1 = *(const float4*)&src[i8 + 4];
    int base2 = (i8 & ~15) >> 1;
    int hi = (i8 & 15) ? 1 : 0;
    __half2* d = (__half2*)dst;
    d[base2 + 0 + hi] = __floats2half2_rn(v0.x * scale, v0.y * scale);
    d[base2 + 2 + hi] = __floats2half2_rn(v0.z * scale, v0.w * scale);
    d[base2 + 4 + hi] = __floats2half2_rn(v1.x * scale, v1.y * scale);
    d[base2 + 6 + hi] = __floats2half2_rn(v1.z * scale, v1.w * scale);
}

__global__ void cvt_all_kernel(const float* xq, const float* xkv,
                               const float* w0, const float* w1,
                               const float* w2, const float* w3,
                               __half* dxq, __half* dxkv,
                               __half* d0, __half* d1, __half* d2, __half* d3,
                               int* flags)
{
    if (blockIdx.x == 0 && threadIdx.x == 0) *flags = 0;
    const int XB = (MROWS * DMODEL) / 8 / 256;   // 4096
    const int WB = (DMODEL * DMODEL) / 8 / 256;  // 512
    int bid = blockIdx.x;
    const float* s; __half* d; int i8;
    if (bid < XB) {
        s = xq;  d = dxq;  i8 = bid * 2048 + threadIdx.x * 8;
    } else if (bid < 2 * XB) {
        s = xkv; d = dxkv; i8 = (bid - XB) * 2048 + threadIdx.x * 8;
    } else {
        int wb = bid - 2 * XB;
        int wi = wb / WB;
        i8 = (wb % WB) * 2048 + threadIdx.x * 8;
        s = (wi == 0) ? w0 : (wi == 1) ? w1 : (wi == 2) ? w2 : w3;
        d = (wi == 0) ? d0 : (wi == 1) ? d1 : (wi == 2) ? d2 : d3;
    }
    cvt_body(s, d, i8, 1.0f);
}

// ---------------- fp16 GEMM core: 128x128x32, 3-stage, 3 CTAs/SM ----------------
// 256 threads, 8 warps of 64x32. GST=48 (24 words: bank sets {0,8,16,24}+{0..6}
// disjoint mod 32 -> conflict-free LDS.64 fragments). smem 73728 B -> 3 CTAs/SM.
#define BM   128
#define BN   128
#define BKH  32
#define GST  48

__device__ __forceinline__ void gemm_core(
    const __half* __restrict__ A, const __half* __restrict__ W,
    void* __restrict__ Cv, float scale, int mode, int bm, int bn)
{
    extern __shared__ __half smh[];
    __half* As = smh;                      // [3][BM][GST]
    __half* Ws = smh + 3 * BM * GST;       // [3][BN][GST]

    const int tid  = threadIdx.x;
    const int lane = tid & 31;
    const int warp = tid >> 5;
    const int wm   = warp >> 2;
    const int wn   = warp & 3;
    const int lr   = lane >> 2;
    const int lc   = lane & 3;

    float acc[4][4][4];
#pragma unroll
    for (int i = 0; i < 4; i++)
#pragma unroll
        for (int j = 0; j < 4; j++)
#pragma unroll
            for (int c = 0; c < 4; c++) acc[i][j][c] = 0.f;

    const int NIT = DMODEL / BKH;   // 32

    auto load_stage = [&](int st, int k0) {
#pragma unroll
        for (int r = 0; r < 2; r++) {
            int id  = tid + r * 256;        // 512 ids: 128 rows x 4 chunks of 8 halves
            int m   = id >> 2;
            int c8  = (id & 3) * 8;
            cp16(&As[(st * BM + m) * GST + c8], &A[(size_t)(bm + m) * DMODEL + k0 + c8]);
        }
#pragma unroll
        for (int r = 0; r < 2; r++) {
            int id  = tid + r * 256;
            int m   = id >> 2;
            int c8  = (id & 3) * 8;
            cp16(&Ws[(st * BN + m) * GST + c8], &W[(size_t)(bn + m) * DMODEL + k0 + c8]);
        }
        asm volatile("cp.async.commit_group;");
    };

    // prologue: stages 0,1,2 in flight; stage 0 made visible
    load_stage(0, 0);
    load_stage(1, BKH);
    load_stage(2, 2 * BKH);
    asm volatile("cp.async.wait_group 2;");
    __syncthreads();

    int cur = 0;   // buffer index = it % 3
    for (int it = 0; it < NIT; it++) {
        const __half* Ab = &As[cur * BM * GST];
        const __half* Wb = &Ws[cur * BN * GST];

#pragma unroll
        for (int kk = 0; kk < 2; kk++) {
            unsigned af[4][4], bf[4][2];
#pragma unroll
            for (int mf = 0; mf < 4; mf++) {
                const int row = wm * 64 + mf * 16 + lr;
                uint2 u0 = *(const uint2*)&Ab[row * GST + kk * 16 + 4 * lc];
                uint2 u1 = *(const uint2*)&Ab[(row + 8) * GST + kk * 16 + 4 * lc];
                af[mf][0] = u0.x; af[mf][1] = u1.x; af[mf][2] = u0.y; af[mf][3] = u1.y;
            }
#pragma unroll
            for (int nf = 0; nf < 4; nf++) {
                const int row = wn * 32 + nf * 8 + lr;
                uint2 u = *(const uint2*)&Wb[row * GST + kk * 16 + 4 * lc];
                bf[nf][0] = u.x; bf[nf][1] = u.y;
            }
#pragma unroll
            for (int mf = 0; mf < 4; mf++)
#pragma unroll
                for (int nf = 0; nf < 4; nf++)
                    mma_f16(acc[mf][nf], af[mf], bf[nf]);
        }

        if (it + 1 < NIT) {
            if (it + 2 < NIT) asm volatile("cp.async.wait_group 1;");  // stage it+1 done
            else              asm volatile("cp.async.wait_group 0;");
            __syncthreads();   // everyone done reading buf cur; stage it+1 visible
            if (it + 3 < NIT) load_stage(cur, (it + 3) * BKH);         // buf cur = (it+3)%3
        }
        cur = (cur == 2) ? 0 : cur + 1;
    }

    // epilogue
#pragma unroll
    for (int mf = 0; mf < 4; mf++) {
#pragma unroll
        for (int half = 0; half < 2; half++) {
            const int m = bm + wm * 64 + mf * 16 + lr + half * 8;
#pragma unroll
            for (int nf = 0; nf < 4; nf++) {
                const int n = bn + wn * 32 + nf * 8 + 2 * lc;
                float c0 = acc[mf][nf][half * 2], c1 = acc[mf][nf][half * 2 + 1];
                if (mode == 0) {
                    float* C = (float*)Cv;
                    *(float2*)&C[(size_t)m * DMODEL + n] = make_float2(c0, c1);
                } else if (mode == 1) {
                    __half* C = (__half*)Cv;
                    const int b = m >> 11, t = m & 2047;
                    const int h = n >> 6;
                    const int hd = n & 63;
                    const int offd = (hd & ~15) + 2 * islot((hd & 15) >> 1);
                    __half2 hv = __floats2half2_rn(c0 * scale, c1 * scale);
                    *(__half2*)&C[(((size_t)(b * NHEADS + h) * TQ + t) << 6) + offd] = hv;
                } else {
                    __half* C = (__half*)Cv;
                    const int b = m >> 11, t = m & 2047;
                    const int h = n >> 6;
                    const int hd0 = n & 63;
                    const int col = (t & ~15) + 2 * islot((t & 15) >> 1) + (t & 1);
                    __half* base = &C[((size_t)(b * NHEADS + h) * HDIM) * (size_t)TK];
                    base[(size_t)hd0 * TK + col]       = __float2half_rn(c0);
                    base[(size_t)(hd0 + 1) * TK + col] = __float2half_rn(c1);
                }
            }
        }
    }
}

__global__ void __launch_bounds__(256, 3)
gemm_qkv(const __half* __restrict__ xq, const __half* __restrict__ xkv,
         const __half* __restrict__ wq, const __half* __restrict__ wk,
         const __half* __restrict__ wv,
         __half* __restrict__ qP, __half* __restrict__ kP, __half* __restrict__ vP,
         float qscale,
         const float* __restrict__ maskF, __half* __restrict__ maskH,
         const unsigned char* __restrict__ kpm, int* __restrict__ flags)
{
    const int bm = blockIdx.y * BM;
    const int bn = blockIdx.x * BN;
    if (blockIdx.z == 0)      { gemm_core(xq,  wq, qP, qscale, 1, bm, bn); return; }
    else if (blockIdx.z == 1) { gemm_core(xkv, wk, kP, 1.0f,   1, bm, bn); return; }
    else if (blockIdx.z == 2) { gemm_core(xkv, wv, vP, 1.0f,   2, bm, bn); return; }

    const int base = blockIdx.y * gridDim.x + blockIdx.x;   // 0..511
    bool nz = false;
#pragma unroll
    for (int r = 0; r < 4; r++) {
        int i8 = (base * 1024 + r * 256 + threadIdx.x) * 8;
        float4 v0 = *(const float4*)&maskF[i8];
        float4 v1 = *(const float4*)&maskF[i8 + 4];
        __half2 h[4];
        h[0] = __floats2half2_rn(v0.x, v0.y);
        h[1] = __floats2half2_rn(v0.z, v0.w);
        h[2] = __floats2half2_rn(v1.x, v1.y);
        h[3] = __floats2half2_rn(v1.z, v1.w);
        *(uint4*)&maskH[i8] = *(uint4*)h;
        nz |= (v0.x != 0.f) | (v0.y != 0.f) | (v0.z != 0.f) | (v0.w != 0.f) |
              (v1.x != 0.f) | (v1.y != 0.f) | (v1.z != 0.f) | (v1.w != 0.f);
    }
    if (__ballot_sync(0xffffffffu, nz)) {
        if ((threadIdx.x & 31) == 0) atomicOr(flags, 1);
    }
    if (base == 0) {
        bool knz = false;
#pragma unroll
        for (int r = 0; r < 2; r++) {
            int i16 = (r * 256 + threadIdx.x) * 16;
            uint4 v = *(const uint4*)&kpm[i16];
            knz |= ((v.x | v.y | v.z | v.w) != 0u);
        }
        if (__ballot_sync(0xffffffffu, knz)) {
            if ((threadIdx.x & 31) == 0) atomicOr(flags, 2);
        }
    }
}

__global__ void __launch_bounds__(256, 3)
gemm_out(const __half* __restrict__ A, const __half* __restrict__ W,
         float* __restrict__ C)
{
    gemm_core(A, W, C, 1.0f, 0, blockIdx.y * BM, blockIdx.x * BN);
}

// ---------------- fused attention: KT=128, Q in registers -----------------------
#define AQ   64
#define KT   128
#define KSTR 80    // 40 words = 8 mod 32 -> conflict-free LDS.64
#define VSTR 144   // 72 words = 8 mod 32 -> conflict-free LDS.64

__global__ void __launch_bounds__(128, 3)
attn_h16(const __half* __restrict__ Q, const __half* __restrict__ K,
         const __half* __restrict__ V, const __half* __restrict__ mask,
         const unsigned char* __restrict__ kpm, __half* __restrict__ O,
         const int* __restrict__ flagsP)
{
    extern __shared__ __half smh[];
    __half* Ks = smh;                      // [2][128][KSTR]
    __half* Vs = smh + 2 * KT * KSTR;      // [64][VSTR]  (V^T: rows=hd)

    const int tid  = threadIdx.x;
    const int lane = tid & 31;
    const int warp = tid >> 5;
    const int lr   = lane >> 2;
    const int lc   = lane & 3;

    const int q0 = blockIdx.x * AQ;
    const int bh = blockIdx.y;
    const int b  = bh >> 4;
    const int h  = bh & 15;

    const bool plain = (*flagsP == 0);

    const __half* Qb = Q + (size_t)bh * TQ * HDIM;
    const __half* Kb = K + (size_t)bh * TK * HDIM;
    const __half* Vb = V + (size_t)bh * HDIM * TK;

    auto cp_K = [&](int st, int kt) {
        const int k0 = kt * KT;
#pragma unroll
        for (int r = 0; r < 8; r++) {
            int id = tid + r * 128;
            int row = id >> 3, c8 = (id & 7) * 8;
            cp16(&Ks[st * KT * KSTR + row * KSTR + c8], &Kb[(size_t)(k0 + row) * HDIM + c8]);
        }
        asm volatile("cp.async.commit_group;");
    };
    auto cp_V = [&](int kt) {
        const int k0 = kt * KT;
#pragma unroll
        for (int r = 0; r < 8; r++) {
            int id = tid + r * 128;
            int row = id >> 4, c8 = (id & 15) * 8;
            cp16(&Vs[row * VSTR + c8], &Vb[(size_t)row * TK + k0 + c8]);
        }
        asm volatile("cp.async.commit_group;");
    };

    cp_K(0, 0);
    cp_V(0);
    cp_K(1, 1);

    unsigned qf[4][4];
#pragma unroll
    for (int kk = 0; kk < 4; kk++) {
        const int row = q0 + warp * 16 + lr;
        uint2 u0 = *(const uint2*)&Qb[(size_t)row * HDIM + kk * 16 + 4 * lc];
        uint2 u1 = *(const uint2*)&Qb[(size_t)(row + 8) * HDIM + kk * 16 + 4 * lc];
        qf[kk][0] = u0.x; qf[kk][1] = u1.x; qf[kk][2] = u0.y; qf[kk][3] = u1.y;
    }

    float m_i[2] = {-INFINITY, -INFINITY};
    float l_i[2] = {0.f, 0.f};
    float o[8][4];
#pragma unroll
    for (int nf = 0; nf < 8; nf++)
#pragma unroll
        for (int c = 0; c < 4; c++) o[nf][c] = 0.f;

    const int NT = TK / KT;   // 16
    for (int kt = 0; kt < NT; kt++) {
        const int k0 = kt * KT;

        if (kt + 1 < NT) asm volatile("cp.async.wait_group 2;");
        else             asm volatile("cp.async.wait_group 1;");
        __syncthreads();

        const __half* Kst = &Ks[(kt & 1) * KT * KSTR];

        float s[16][4];
#pragma unroll
        for (int nf = 0; nf < 16; nf++)
#pragma unroll
            for (int c = 0; c < 4; c++) s[nf][c] = 0.f;

#pragma unroll
        for (int kk = 0; kk < 4; kk++) {
#pragma unroll
            for (int nf = 0; nf < 16; nf++) {
                unsigned bf[2];
                uint2 u = *(const uint2*)&Kst[(nf * 8 + lr) * KSTR + kk * 16 + 4 * lc];
                bf[0] = u.x; bf[1] = u.y;
                mma_f16(s[nf], qf[kk], bf);
            }
        }

        if (!plain) {
            uchar2 kp[16];
#pragma unroll
            for (int nf = 0; nf < 16; nf++)
                kp[nf] = *(const uchar2*)&kpm[(size_t)b * TK + k0 + nf * 8 + 2 * lc];
#pragma unroll
            for (int hf = 0; hf < 2; hf++) {
                const int qg = q0 + warp * 16 + lr + hf * 8;
                const __half* mrow = &mask[(size_t)qg * TK + k0];
#pragma unroll
                for (int nf = 0; nf < 16; nf++) {
                    float2 mv = __half22float2(*(const __half2*)&mrow[nf * 8 + 2 * lc]);
                    float v0 = s[nf][hf * 2]     + mv.x * LOG2E;
                    float v1 = s[nf][hf * 2 + 1] + mv.y * LOG2E;
                    if (kp[nf].x) v0 = -INFINITY;
                    if (kp[nf].y) v1 = -INFINITY;
                    s[nf][hf * 2]     = v0;
                    s[nf][hf * 2 + 1] = v1;
                }
            }
        }

        unsigned e[16][2];
#pragma unroll
        for (int hf = 0; hf < 2; hf++) {
            float mx = -INFINITY;
#pragma unroll
            for (int nf = 0; nf < 16; nf++)
                mx = fmaxf(mx, fmaxf(s[nf][hf * 2], s[nf][hf * 2 + 1]));
            mx = fmaxf(mx, __shfl_xor_sync(0xffffffffu, mx, 1));
            mx = fmaxf(mx, __shfl_xor_sync(0xffffffffu, mx, 2));
            float mnew = fmaxf(m_i[hf], mx);
            float alpha, rs = 0.f;
            if (mnew == -INFINITY) {
                alpha = 1.f;
#pragma unroll
                for (int nf = 0; nf < 16; nf++) e[nf][hf] = 0u;
            } else {
                alpha = ex2f(m_i[hf] - mnew);
#pragma unroll
                for (int nf = 0; nf < 16; nf++) {
                    __half2 xh = __floats2half2_rn(s[nf][hf * 2] - mnew,
                                                   s[nf][hf * 2 + 1] - mnew);
                    __half2 ph = h2exp2(xh);
                    e[nf][hf] = *(unsigned*)&ph;
                    float2 pf = __half22float2(ph);
                    rs += pf.x + pf.y;
                }
            }
            rs += __shfl_xor_sync(0xffffffffu, rs, 1);
            rs += __shfl_xor_sync(0xffffffffu, rs, 2);
            l_i[hf] = l_i[hf] * alpha + rs;
            m_i[hf] = mnew;
#pragma unroll
            for (int nf = 0; nf < 8; nf++) {
                o[nf][hf * 2]     *= alpha;
                o[nf][hf * 2 + 1] *= alpha;
            }
        }

        if (kt + 1 < NT) asm volatile("cp.async.wait_group 1;");
        else             asm volatile("cp.async.wait_group 0;");
        __syncthreads();

#pragma unroll
        for (int kb = 0; kb < 8; kb++) {
            unsigned af[4];
            af[0] = e[2 * kb][0];
            af[1] = e[2 * kb][1];
            af[2] = e[2 * kb + 1][0];
            af[3] = e[2 * kb + 1][1];
#pragma unroll
            for (int nf = 0; nf < 8; nf++) {
                unsigned bf[2];
                uint2 u = *(const uint2*)&Vs[(nf * 8 + lr) * VSTR + kb * 16 + 4 * lc];
                bf[0] = u.x; bf[1] = u.y;
                mma_f16(o[nf], af, bf);
            }
        }
        __syncthreads();

        if (kt + 1 < NT) cp_V(kt + 1);
        if (kt + 2 < NT) cp_K(kt & 1, kt + 2);
    }

    // finalize: (b,t,dmodel-interleaved) fp16
#pragma unroll
    for (int hf = 0; hf < 2; hf++) {
        const float inv = (l_i[hf] > 0.f) ? (1.f / l_i[hf]) : 0.f;
        const int t = q0 + warp * 16 + lr + hf * 8;
#pragma unroll
        for (int nf = 0; nf < 8; nf++) {
            const int n = h * HDIM + nf * 8 + 2 * lc;
            const int offd = (n & ~15) + 2 * islot((n & 15) >> 1);
            __half2 hv = __floats2half2_rn(o[nf][hf * 2] * inv, o[nf][hf * 2 + 1] * inv);
            *(__half2*)&O[((size_t)(b * TQ + t)) * DMODEL + offd] = hv;
        }
    }
}

// ---------------- launch --------------------------------------------------------
extern "C" void kernel_launch(void* const* d_in, const int* in_sizes, int n_in,
                              void* d_out, int out_size)
{
    const float* x_q   = (const float*)d_in[0];
    const float* x_kv  = (const float*)d_in[1];
    const float* amask = (const float*)d_in[2];
    const unsigned char* kpm = (const unsigned char*)d_in[3];
    const float* Wq = (const float*)d_in[4];
    const float* Wk = (const float*)d_in[5];
    const float* Wv = (const float*)d_in[6];
    const float* Wo = (const float*)d_in[7];
    float* out = (float*)d_out;

    __half *qP, *kP, *vP, *oP, *xqP, *xkvP, *wqP, *wkP, *wvP, *woP, *mP;
    int* flagsP;
    cudaGetSymbolAddress((void**)&qP,  h_Q);
    cudaGetSymbolAddress((void**)&kP,  h_K);
    cudaGetSymbolAddress((void**)&vP,  h_V);
    cudaGetSymbolAddress((void**)&oP,  h_O);
    cudaGetSymbolAddress((void**)&xqP, h_Xq);
    cudaGetSymbolAddress((void**)&xkvP,h_Xkv);
    cudaGetSymbolAddress((void**)&wqP, h_Wq);
    cudaGetSymbolAddress((void**)&wkP, h_Wk);
    cudaGetSymbolAddress((void**)&wvP, h_Wv);
    cudaGetSymbolAddress((void**)&woP, h_Wo);
    cudaGetSymbolAddress((void**)&mP,  h_Mask);
    cudaGetSymbolAddress((void**)&flagsP, g_flags);

    const int XB = (MROWS * DMODEL) / 8 / 256;   // 4096
    const int WB = (DMODEL * DMODEL) / 8 / 256;  // 512
    cvt_all_kernel<<<2 * XB + 4 * WB, 256>>>(x_q, x_kv, Wq, Wk, Wv, Wo,
                                             xqP, xkvP, wqP, wkP, wvP, woP, flagsP);

    const int gemm_smem = 3 * (BM + BN) * GST * (int)sizeof(__half);   // 73728
    cudaFuncSetAttribute(gemm_qkv, cudaFuncAttributeMaxDynamicSharedMemorySize, gemm_smem);
    cudaFuncSetAttribute(gemm_out, cudaFuncAttributeMaxDynamicSharedMemorySize, gemm_smem);

    const float qscale = 0.125f * LOG2E;

    dim3 gqkv(DMODEL / BN, MROWS / BM, 4);   // (8, 64, 4)
    gemm_qkv<<<gqkv, 256, gemm_smem>>>(xqP, xkvP, wqP, wkP, wvP, qP, kP, vP, qscale,
                                       amask, mP, kpm, flagsP);

    const int attn_smem = (2 * KT * KSTR + HDIM * VSTR) * (int)sizeof(__half);  // 59392
    cudaFuncSetAttribute(attn_h16, cudaFuncAttributeMaxDynamicSharedMemorySize, attn_smem);
    dim3 ga(TQ / AQ, BATCH * NHEADS);     // (32, 64)
    attn_h16<<<ga, 128, attn_smem>>>(qP, kP, vP, mP, kpm, oP, flagsP);

    dim3 gout(DMODEL / BN, MROWS / BM);   // (8, 64)
    gemm_out<<<gout, 256, gemm_smem>>>(oP, woP, out);
}